// round 2
// baseline (speedup 1.0000x reference)
#include <cuda_runtime.h>

#define HW 4096
#define NR 2048
#define NL 16

// ---------------- device scratch (no allocations allowed) ----------------
__device__ float d_S[NR];                       // x-row sums
__device__ int   d_gcount[NL], d_gstart[NL];
__device__ int   d_nvalid;
__device__ int   d_prow[NR], d_pgrp[NR];        // per grouped-position
__device__ float d_pwq[NR], d_pbq[NR], d_pwk[NR], d_pbk[NR], d_pwv[NR], d_pbv[NR];
__device__ int   d_pmq[NR], d_pnk[NR], d_pnv[NR];
__device__ float d_pSq[NR], d_pSk[NR];
__device__ float d_cst[NR];
__device__ float d_scores[(long long)NR * NR];  // scores, then softmax*wv coeffs in-place

#define MAXWS 512
#define MAXWO 64
__device__ int d_wsG[MAXWS], d_wsA[MAXWS], d_wsB[MAXWS], d_nWorkS;
__device__ int d_woG[MAXWO], d_woA[MAXWO], d_nWorkO;

// ---------------- f32x2 helpers (FFMA2: 2x fp32 FMA rate on sm_103a) -----
__device__ __forceinline__ unsigned long long dup2(float v) {
    unsigned long long r;
    asm("mov.b64 %0, {%1, %1};" : "=l"(r) : "f"(v));
    return r;
}
__device__ __forceinline__ void fma2(unsigned long long &d, unsigned long long a,
                                     unsigned long long b) {
    asm("fma.rn.f32x2 %0, %1, %2, %0;" : "+l"(d) : "l"(a), "l"(b));
}
__device__ __forceinline__ float2 unpk(unsigned long long v) {
    float2 r;
    asm("mov.b64 {%0, %1}, %2;" : "=f"(r.x), "=f"(r.y) : "l"(v));
    return r;
}

// ---------------- setup: count + prefix + worklists, one block -----------
__global__ void setupKernel(const int* __restrict__ labels) {
    __shared__ int cnt[NL];
    int t = threadIdx.x;
    if (t < NL) cnt[t] = 0;
    __syncthreads();
    for (int i = t; i < NR; i += 256) {
        int l = labels[i];
        if (l >= 0) atomicAdd(&cnt[l], 1);
    }
    __syncthreads();
    if (t == 0) {
        int s = 0;
        for (int l = 0; l < NL; l++) {
            d_gcount[l] = cnt[l];
            d_gstart[l] = s;
            s += cnt[l];
        }
        d_nvalid = s;
        int n = 0;
        for (int l = 0; l < NL; l++) {
            int T = (cnt[l] + 127) / 128;
            for (int a = 0; a < T; a++)
                for (int b = 0; b < T; b++)
                    if (n < MAXWS) { d_wsG[n] = l; d_wsA[n] = a; d_wsB[n] = b; n++; }
        }
        d_nWorkS = n;
        n = 0;
        for (int l = 0; l < NL; l++) {
            int T = (cnt[l] + 127) / 128;
            for (int a = 0; a < T; a++)
                if (n < MAXWO) { d_woG[n] = l; d_woA[n] = a; n++; }
        }
        d_nWorkO = n;
    }
}

__global__ void rowsumKernel(const float* __restrict__ x) {
    int m = blockIdx.x;
    const float4* p = (const float4*)(x + (long long)m * HW);
    float s = 0.f;
    for (int i = threadIdx.x; i < HW / 4; i += 128) {
        float4 v = p[i];
        s += (v.x + v.y) + (v.z + v.w);
    }
    __shared__ float red[128];
    red[threadIdx.x] = s;
    __syncthreads();
    for (int o = 64; o > 0; o >>= 1) {
        if (threadIdx.x < o) red[threadIdx.x] += red[threadIdx.x + o];
        __syncthreads();
    }
    if (threadIdx.x == 0) d_S[m] = red[0];
}

// deterministic grouping: rank by smem scan
__global__ void scatterKernel(const int* __restrict__ labels,
                              const float* __restrict__ w,
                              const float* __restrict__ bb) {
    __shared__ int sl[NR];
    for (int j = threadIdx.x; j < NR; j += 128) sl[j] = labels[j];
    __syncthreads();
    int i = blockIdx.x * 128 + threadIdx.x;
    int l = sl[i];
    if (l < 0) return;
    int rank = 0;
    for (int j = 0; j < i; j++) rank += (sl[j] == l);
    int pos = d_gstart[l] + rank;
    d_prow[pos] = i;
    d_pgrp[pos] = l;
    int jq = i % 768;            int mq = (i / 768) * 256 + jq / 3;
    int rk = i + 2048; int jk = rk % 768; int nk = (rk / 768) * 256 + jk / 3;
    int rv = i + 4096; int jv = rv % 768; int nv = (rv / 768) * 256 + jv / 3;
    d_pwq[pos] = w[jq]; d_pbq[pos] = bb[jq];
    d_pwk[pos] = w[jk]; d_pbk[pos] = bb[jk];
    d_pwv[pos] = w[jv]; d_pbv[pos] = bb[jv];
    d_pmq[pos] = mq; d_pnk[pos] = nk; d_pnv[pos] = nv;
    d_pSq[pos] = d_S[mq]; d_pSk[pos] = d_S[nk];
}

// affine part of scores: wq*bk*Sq + bq*wk*Sk + bq*bk*HW  (warp per row)
__global__ void scoreInitKernel() {
    int p = blockIdx.x * 8 + (threadIdx.x >> 5);
    int lane = threadIdx.x & 31;
    if (p >= d_nvalid) return;
    int g = d_pgrp[p], gs = d_gstart[g], gc = d_gcount[g];
    float wq = d_pwq[p], bq = d_pbq[p], Sq = d_pSq[p];
    long long ro = (long long)p * NR;
    for (int bl = lane; bl < gc; bl += 32) {
        int q = gs + bl;
        d_scores[ro + bl] = wq * d_pbk[q] * Sq + bq * d_pwk[q] * d_pSk[q]
                          + bq * d_pbk[q] * (float)HW;
    }
}

// ---------------- scores GEMM: per-group Gram, 128x128, splitK=8 ---------
// double-buffered smem pipeline, one __syncthreads per k-chunk
__global__ __launch_bounds__(256) void scoresGemmKernel(const float* __restrict__ x) {
    int wi = blockIdx.x;
    if (wi >= d_nWorkS) return;
    int g = d_wsG[wi];
    int gs = d_gstart[g], gc = d_gcount[g];
    int a0 = d_wsA[wi] * 128, b0 = d_wsB[wi] * 128;
    int k0b = blockIdx.y * (HW / 8);

    __shared__ float As[2][8][132], Bs[2][8][132];
    int tid = threadIdx.x;
    int ty = tid >> 4, tx = tid & 15;
    int lr = tid >> 1, lk = (tid & 1) * 4;

    const float* ap  = (a0 + lr < gc) ? x + (long long)d_pmq[gs + a0 + lr] * HW + k0b + lk : 0;
    const float* bpp = (b0 + lr < gc) ? x + (long long)d_pnk[gs + b0 + lr] * HW + k0b + lk : 0;

    unsigned long long acc[8][4];
#pragma unroll
    for (int r = 0; r < 8; r++)
#pragma unroll
        for (int c = 0; c < 4; c++) acc[r][c] = 0ull;

    float4 z4 = make_float4(0, 0, 0, 0);
    float4 va = ap  ? *(const float4*)ap  : z4;
    float4 vb = bpp ? *(const float4*)bpp : z4;
    As[0][lk + 0][lr] = va.x; As[0][lk + 1][lr] = va.y;
    As[0][lk + 2][lr] = va.z; As[0][lk + 3][lr] = va.w;
    Bs[0][lk + 0][lr] = vb.x; Bs[0][lk + 1][lr] = vb.y;
    Bs[0][lk + 2][lr] = vb.z; Bs[0][lk + 3][lr] = vb.w;
    __syncthreads();

    for (int kc = 0; kc < 64; kc++) {
        int cur = kc & 1;
        if (kc < 63) {
            va = ap  ? *(const float4*)(ap  + (kc + 1) * 8) : z4;
            vb = bpp ? *(const float4*)(bpp + (kc + 1) * 8) : z4;
        }
#pragma unroll
        for (int kk = 0; kk < 8; kk++) {
            unsigned long long ad[8], bd[4];
#pragma unroll
            for (int r = 0; r < 8; r++) ad[r] = dup2(As[cur][kk][ty * 8 + r]);
#pragma unroll
            for (int c = 0; c < 4; c++)
                bd[c] = *(const unsigned long long*)&Bs[cur][kk][tx * 8 + c * 2];
#pragma unroll
            for (int r = 0; r < 8; r++)
#pragma unroll
                for (int c = 0; c < 4; c++) fma2(acc[r][c], ad[r], bd[c]);
        }
        if (kc < 63) {
            int nx = cur ^ 1;
            As[nx][lk + 0][lr] = va.x; As[nx][lk + 1][lr] = va.y;
            As[nx][lk + 2][lr] = va.z; As[nx][lk + 3][lr] = va.w;
            Bs[nx][lk + 0][lr] = vb.x; Bs[nx][lk + 1][lr] = vb.y;
            Bs[nx][lk + 2][lr] = vb.z; Bs[nx][lk + 3][lr] = vb.w;
            __syncthreads();
        }
    }

#pragma unroll
    for (int r = 0; r < 8; r++) {
        int al = a0 + ty * 8 + r;
        if (al >= gc) continue;
        int p = gs + al;
        float wq = d_pwq[p];
        long long ro = (long long)p * NR;
#pragma unroll
        for (int c = 0; c < 4; c++) {
            float2 v = unpk(acc[r][c]);
            int col = b0 + tx * 8 + c * 2;
            if (col < gc)     atomicAdd(&d_scores[ro + col],     wq * d_pwk[gs + col] * v.x);
            if (col + 1 < gc) atomicAdd(&d_scores[ro + col + 1], wq * d_pwk[gs + col + 1] * v.y);
        }
    }
}

// ---------------- softmax + fold wv/bv, warp per row ---------------------
__global__ void softmaxKernel() {
    int p = blockIdx.x * 8 + (threadIdx.x >> 5);
    int lane = threadIdx.x & 31;
    if (p >= d_nvalid) return;
    int g = d_pgrp[p], gs = d_gstart[g], gc = d_gcount[g];
    long long ro = (long long)p * NR;

    float m = -3.4e38f;
    for (int bl = lane; bl < gc; bl += 32) m = fmaxf(m, d_scores[ro + bl]);
#pragma unroll
    for (int o = 16; o > 0; o >>= 1) m = fmaxf(m, __shfl_xor_sync(0xffffffffu, m, o));

    float sum = 0.f, cs = 0.f;
    for (int bl = lane; bl < gc; bl += 32) {
        float e = expf(d_scores[ro + bl] - m);
        d_scores[ro + bl] = e;
        sum += e;
        cs += e * d_pbv[gs + bl];
    }
#pragma unroll
    for (int o = 16; o > 0; o >>= 1) {
        sum += __shfl_xor_sync(0xffffffffu, sum, o);
        cs  += __shfl_xor_sync(0xffffffffu, cs, o);
    }
    float inv = 1.0f / sum;
    for (int bl = lane; bl < gc; bl += 32)
        d_scores[ro + bl] *= inv * d_pwv[gs + bl];
    if (lane == 0) d_cst[p] = cs * inv;
}

// ---------------- out GEMM: coeff (g x g) @ Xv (g x 4096), dbl-buffered --
__global__ __launch_bounds__(256) void outGemmKernel(const float* __restrict__ x,
                                                     float* __restrict__ out) {
    int wi = blockIdx.x;
    if (wi >= d_nWorkO) return;
    int g = d_woG[wi];
    int gs = d_gstart[g], gc = d_gcount[g];
    int a0 = d_woA[wi] * 128;
    int t0 = blockIdx.y * 128;

    __shared__ float Cs[2][8][132], Xs[2][8][132];
    int tid = threadIdx.x, ty = tid >> 4, tx = tid & 15;
    int lr = tid >> 1, lk = (tid & 1) * 4;       // Cs loader
    int xk = tid >> 5, xc = (tid & 31) * 4;      // Xs loader

    unsigned long long acc[8][4];
#pragma unroll
    for (int r = 0; r < 8; r++)
#pragma unroll
        for (int c = 0; c < 4; c++) acc[r][c] = 0ull;

    long long crow = (a0 + lr < gc) ? (long long)(gs + a0 + lr) * NR : -1;
    int nIter = (gc + 7) >> 3;
    float4 z4 = make_float4(0, 0, 0, 0);

    // prefetch it=0
    float4 vc = z4, vx;
    {
        int b0 = 0;
        if (crow >= 0) {
            vc = *(const float4*)&d_scores[crow + b0 + lk];
            if (b0 + lk + 0 >= gc) vc.x = 0.f;
            if (b0 + lk + 1 >= gc) vc.y = 0.f;
            if (b0 + lk + 2 >= gc) vc.z = 0.f;
            if (b0 + lk + 3 >= gc) vc.w = 0.f;
        }
        int bm = b0 + xk;
        int vrow = (bm < gc) ? d_pnv[gs + bm] : 0;
        vx = *(const float4*)&x[(long long)vrow * HW + t0 + xc];
    }
    Cs[0][lk + 0][lr] = vc.x; Cs[0][lk + 1][lr] = vc.y;
    Cs[0][lk + 2][lr] = vc.z; Cs[0][lk + 3][lr] = vc.w;
    *(float4*)&Xs[0][xk][xc] = vx;
    __syncthreads();

    for (int it = 0; it < nIter; it++) {
        int cur = it & 1;
        if (it + 1 < nIter) {
            int b0 = (it + 1) * 8;
            vc = z4;
            if (crow >= 0) {
                vc = *(const float4*)&d_scores[crow + b0 + lk];
                if (b0 + lk + 0 >= gc) vc.x = 0.f;
                if (b0 + lk + 1 >= gc) vc.y = 0.f;
                if (b0 + lk + 2 >= gc) vc.z = 0.f;
                if (b0 + lk + 3 >= gc) vc.w = 0.f;
            }
            int bm = b0 + xk;
            int vrow = (bm < gc) ? d_pnv[gs + bm] : 0;
            vx = *(const float4*)&x[(long long)vrow * HW + t0 + xc];
        }
#pragma unroll
        for (int kk = 0; kk < 8; kk++) {
            unsigned long long ad[8], bd[4];
#pragma unroll
            for (int r = 0; r < 8; r++) ad[r] = dup2(Cs[cur][kk][ty * 8 + r]);
#pragma unroll
            for (int c = 0; c < 4; c++)
                bd[c] = *(const unsigned long long*)&Xs[cur][kk][tx * 8 + c * 2];
#pragma unroll
            for (int r = 0; r < 8; r++)
#pragma unroll
                for (int c = 0; c < 4; c++) fma2(acc[r][c], ad[r], bd[c]);
        }
        if (it + 1 < nIter) {
            int nx = cur ^ 1;
            Cs[nx][lk + 0][lr] = vc.x; Cs[nx][lk + 1][lr] = vc.y;
            Cs[nx][lk + 2][lr] = vc.z; Cs[nx][lk + 3][lr] = vc.w;
            *(float4*)&Xs[nx][xk][xc] = vx;
            __syncthreads();
        }
    }

#pragma unroll
    for (int r = 0; r < 8; r++) {
        int al = a0 + ty * 8 + r;
        if (al >= gc) continue;
        int p = gs + al;
        int row = d_prow[p];
        float cst = d_cst[p];
        float* op = out + (long long)row * HW + t0 + tx * 8;
#pragma unroll
        for (int c = 0; c < 4; c++) {
            float2 v = unpk(acc[r][c]);
            op[c * 2]     = v.x + cst;
            op[c * 2 + 1] = v.y + cst;
        }
    }
}

// ---------------- launch ----------------
extern "C" void kernel_launch(void* const* d_in, const int* in_sizes, int n_in,
                              void* d_out, int out_size) {
    const float* x      = (const float*)d_in[0];
    const int*   labels = (const int*)d_in[1];
    const float* w      = (const float*)d_in[2];
    const float* bb     = (const float*)d_in[3];
    float* out = (float*)d_out;

    cudaMemsetAsync(d_out, 0, (size_t)out_size * sizeof(float), 0);
    rowsumKernel<<<NR, 128>>>(x);
    setupKernel<<<1, 256>>>(labels);
    scatterKernel<<<16, 128>>>(labels, w, bb);
    scoreInitKernel<<<256, 256>>>();
    dim3 gsGrid(512, 8);
    scoresGemmKernel<<<gsGrid, 256>>>(x);
    softmaxKernel<<<256, 256>>>();
    dim3 goGrid(64, 32);
    outGemmKernel<<<goGrid, 256>>>(x, out);
    (void)in_sizes; (void)n_in;
}